// round 12
// baseline (speedup 1.0000x reference)
#include <cuda_runtime.h>
#include <cuda_fp16.h>
#include <mma.h>
#include <cstdint>

using namespace nvcuda;

#define N_NODES 100000
#define N_EDGES 1600000
#define HID 128
#define NUM_LAYERS 10
#define NUM_GRAPHS 64
#define NUM_CLASSES 2

// ---------------- scratch (device globals; no runtime allocation) ----------------
// g_h / g_hh / g_hl padded by 128 rows so tail-block wmma frag loads never fault.
__device__ __align__(16) float g_x[(size_t)N_NODES * HID];
__device__ __align__(16) float g_h[(size_t)(N_NODES + 128) * HID];
__device__ __align__(16) __half g_hh[(size_t)(N_NODES + 128) * HID];
__device__ __align__(16) __half g_hl[(size_t)(N_NODES + 128) * HID];
__device__ __align__(16) __half g_w1h[NUM_LAYERS * HID * HID];
__device__ __align__(16) __half g_w1l[NUM_LAYERS * HID * HID];
__device__ __align__(16) __half g_w2h[NUM_LAYERS * HID * HID];
__device__ __align__(16) __half g_w2l[NUM_LAYERS * HID * HID];
__device__ unsigned int g_hmax[NUM_LAYERS];
__device__ int   g_deg[N_NODES];
__device__ int   g_rowptr[N_NODES + 1];
__device__ int   g_fill[N_NODES];
__device__ int   g_ssrc[N_EDGES];
__device__ int   g_bsums[256];
__device__ __align__(16) float g_pool[NUM_GRAPHS * HID];
__device__ float g_cnt[NUM_GRAPHS];
__device__ __align__(16) float g_cls[NUM_GRAPHS * HID];

#define W_SCALE 256.0f
#define W_SCALE_INV 0.00390625f

// scale from layer max: s = 2^(11-e) with max = f*2^e, f in [0.5,1) -> max*s in [1024,2048)
__device__ __forceinline__ float layer_scale(int layer) {
    float m = __uint_as_float(g_hmax[layer]);
    if (m < 1e-30f) return 1.0f;
    int e;
    frexpf(m, &e);
    return ldexpf(1.0f, 11 - e);
}
__device__ __forceinline__ float layer_scale_inv(int layer) {
    float m = __uint_as_float(g_hmax[layer]);
    if (m < 1e-30f) return 1.0f;
    int e;
    frexpf(m, &e);
    return ldexpf(1.0f, e - 11);
}

// ---------------- weight pre-split (once per launch), scaled by 2^8 ----------------
__global__ void wprep_kernel(const float* __restrict__ W1,
                             const float* __restrict__ W2) {
    int i = blockIdx.x * blockDim.x + threadIdx.x;
    if (i < NUM_LAYERS * HID * HID) {
        float w = W1[i] * W_SCALE;
        __half h = __float2half_rn(w);
        g_w1h[i] = h;
        g_w1l[i] = __float2half_rn(w - __half2float(h));
        w = W2[i] * W_SCALE;
        h = __float2half_rn(w);
        g_w2h[i] = h;
        g_w2l[i] = __float2half_rn(w - __half2float(h));
    }
}

// ---------------- CSR build ----------------
__global__ void zero_kernel() {
    int i = blockIdx.x * blockDim.x + threadIdx.x;
    if (i < N_NODES) g_deg[i] = 0;
    if (i < NUM_GRAPHS * HID) g_pool[i] = 0.f;
    if (i < NUM_GRAPHS) g_cnt[i] = 0.f;
    if (i < NUM_LAYERS) g_hmax[i] = 0u;
}

__global__ void hist_kernel(const int* __restrict__ dst) {
    int e = blockIdx.x * blockDim.x + threadIdx.x;
    if (e < N_EDGES) atomicAdd(&g_deg[dst[e]], 1);
}

__global__ void scan1_kernel() {
    __shared__ int s[512];
    int tid = threadIdx.x;
    int i = blockIdx.x * 512 + tid;
    int v = (i < N_NODES) ? g_deg[i] : 0;
    s[tid] = v;
    __syncthreads();
    for (int off = 1; off < 512; off <<= 1) {
        int add = (tid >= off) ? s[tid - off] : 0;
        __syncthreads();
        s[tid] += add;
        __syncthreads();
    }
    if (i < N_NODES) g_rowptr[i] = s[tid] - v;
    if (tid == 511) g_bsums[blockIdx.x] = s[511];
}

__global__ void scan2_kernel(int nblk) {
    __shared__ int s[256];
    int tid = threadIdx.x;
    int v = (tid < nblk) ? g_bsums[tid] : 0;
    s[tid] = v;
    __syncthreads();
    for (int off = 1; off < 256; off <<= 1) {
        int add = (tid >= off) ? s[tid - off] : 0;
        __syncthreads();
        s[tid] += add;
        __syncthreads();
    }
    if (tid < nblk) g_bsums[tid] = s[tid] - v;
}

__global__ void scan3_kernel() {
    int i = blockIdx.x * blockDim.x + threadIdx.x;
    if (i < N_NODES) {
        int rp = g_rowptr[i] + g_bsums[i >> 9];
        g_rowptr[i] = rp;
        g_fill[i] = rp;
    }
    if (i == 0) g_rowptr[N_NODES] = N_EDGES;
}

__global__ void scatter_kernel(const int* __restrict__ src,
                               const int* __restrict__ dst) {
    int e = blockIdx.x * blockDim.x + threadIdx.x;
    if (e < N_EDGES) {
        int d = dst[e];
        int p = atomicAdd(&g_fill[d], 1);
        g_ssrc[p] = src[e];
    }
}

// ---------------- aggregation: h[v] = (1+eps)*x[v] + sum_in x[u]; track max -------
__global__ void aggr_kernel(const float* __restrict__ xin_ext,
                            const float* __restrict__ eps, int layer, int use_gx) {
    int gw = (blockIdx.x * blockDim.x + threadIdx.x) >> 5;
    int lane = threadIdx.x & 31;
    if (gw >= N_NODES) return;
    const float* x = use_gx ? g_x : xin_ext;
    float ep1 = 1.0f + eps[layer];
    const float4* xv = (const float4*)x;
    float4 b = __ldg(&xv[(size_t)gw * 32 + lane]);
    float4 a0 = make_float4(b.x * ep1, b.y * ep1, b.z * ep1, b.w * ep1);
    float4 a1 = make_float4(0.f, 0.f, 0.f, 0.f);
    float4 a2 = a1, a3 = a1;
    int s = g_rowptr[gw], e = g_rowptr[gw + 1];
    int i = s;
    for (; i + 4 <= e; i += 4) {
        int s0 = g_ssrc[i], s1 = g_ssrc[i + 1], s2 = g_ssrc[i + 2], s3 = g_ssrc[i + 3];
        float4 v0 = __ldg(&xv[(size_t)s0 * 32 + lane]);
        float4 v1 = __ldg(&xv[(size_t)s1 * 32 + lane]);
        float4 v2 = __ldg(&xv[(size_t)s2 * 32 + lane]);
        float4 v3 = __ldg(&xv[(size_t)s3 * 32 + lane]);
        a0.x += v0.x; a0.y += v0.y; a0.z += v0.z; a0.w += v0.w;
        a1.x += v1.x; a1.y += v1.y; a1.z += v1.z; a1.w += v1.w;
        a2.x += v2.x; a2.y += v2.y; a2.z += v2.z; a2.w += v2.w;
        a3.x += v3.x; a3.y += v3.y; a3.z += v3.z; a3.w += v3.w;
    }
    for (; i < e; i++) {
        int s0 = g_ssrc[i];
        float4 v0 = __ldg(&xv[(size_t)s0 * 32 + lane]);
        a1.x += v0.x; a1.y += v0.y; a1.z += v0.z; a1.w += v0.w;
    }
    a0.x += a1.x + a2.x + a3.x;
    a0.y += a1.y + a2.y + a3.y;
    a0.z += a1.z + a2.z + a3.z;
    a0.w += a1.w + a2.w + a3.w;
    ((float4*)g_h)[(size_t)gw * 32 + lane] = a0;
    // warp-max of |h| -> g_hmax[layer]
    float m = fmaxf(fmaxf(fabsf(a0.x), fabsf(a0.y)), fmaxf(fabsf(a0.z), fabsf(a0.w)));
#pragma unroll
    for (int off = 16; off > 0; off >>= 1)
        m = fmaxf(m, __shfl_xor_sync(0xffffffffu, m, off));
    if (lane == 0) atomicMax(&g_hmax[layer], __float_as_uint(m));
}

// ---------------- split h*s into fp16 hi/lo ----------------
__global__ void split_kernel(int layer) {
    int i = blockIdx.x * blockDim.x + threadIdx.x;   // float4 index
    if (i >= N_NODES * 32) return;
    float s = layer_scale(layer);
    float4 v = ((const float4*)g_h)[i];
    v.x *= s; v.y *= s; v.z *= s; v.w *= s;
    __half hx = __float2half_rn(v.x), hy = __float2half_rn(v.y);
    __half hz = __float2half_rn(v.z), hw = __float2half_rn(v.w);
    ((__half2*)g_hh)[i * 2]     = __halves2half2(hx, hy);
    ((__half2*)g_hh)[i * 2 + 1] = __halves2half2(hz, hw);
    ((__half2*)g_hl)[i * 2] = __halves2half2(
        __float2half_rn(v.x - __half2float(hx)),
        __float2half_rn(v.y - __half2float(hy)));
    ((__half2*)g_hl)[i * 2 + 1] = __halves2half2(
        __float2half_rn(v.z - __half2float(hz)),
        __float2half_rn(v.w - __half2float(hw)));
}

// ================= wmma 3xFP16 fused MLP (scaled) ================================
// All weight/activation pointers derived from device symbols IN DEVICE CODE
// (host-side arithmetic on __device__ symbols silently reads the host shadow!).
#define WM_BM 64
#define TSH 136   // half leading dim (mult of 8)

typedef wmma::fragment<wmma::matrix_a, 16, 16, 16, __half, wmma::row_major> AH;
typedef wmma::fragment<wmma::matrix_b, 16, 16, 16, __half, wmma::row_major> BH;
typedef wmma::fragment<wmma::accumulator, 16, 16, 16, float> CH;

__global__ void __launch_bounds__(128)
mlp_h3_kernel(const float* __restrict__ xin_ext,
              const float* __restrict__ b1, const float* __restrict__ b2,
              int add_h, int use_gx, int layer) {
    __shared__ __align__(32) __half Th[4][16 * TSH];   // 17.4 KB
    __shared__ __align__(32) __half Tl[4][16 * TSH];   // 17.4 KB
    __shared__ __align__(32) float  Cs[4][16 * 16];    //  4.1 KB

    const float* xin = use_gx ? g_x : xin_ext;
    const __half* W1h = g_w1h + (size_t)layer * HID * HID;
    const __half* W1l = g_w1l + (size_t)layer * HID * HID;
    const __half* W2h = g_w2h + (size_t)layer * HID * HID;
    const __half* W2l = g_w2l + (size_t)layer * HID * HID;

    int w = threadIdx.x >> 5;
    int lane = threadIdx.x & 31;
    int wrow = blockIdx.x * WM_BM + w * 16;   // may exceed N_NODES; arrays padded
    __half* th = Th[w];
    __half* tl = Tl[w];
    float*  cs = Cs[w];

    float s = layer_scale(layer);
    float inv_all = layer_scale_inv(layer) * W_SCALE_INV;   // 1/(s*256)

    AH ah, al;
    BH bh, bl;

    // ---- GEMM1: cs = (h*s)@(W1*256);  T_scaled = relu(cs*inv_all + b1)*s
#pragma unroll
    for (int nt = 0; nt < 8; nt++) {
        CH c;
        wmma::fill_fragment(c, 0.f);
#pragma unroll
        for (int k = 0; k < 8; k++) {
            wmma::load_matrix_sync(ah, g_hh + (size_t)wrow * HID + k * 16, HID);
            wmma::load_matrix_sync(al, g_hl + (size_t)wrow * HID + k * 16, HID);
            wmma::load_matrix_sync(bh, W1h + (size_t)(k * 16) * HID + nt * 16, HID);
            wmma::load_matrix_sync(bl, W1l + (size_t)(k * 16) * HID + nt * 16, HID);
            wmma::mma_sync(c, ah, bh, c);
            wmma::mma_sync(c, al, bh, c);
            wmma::mma_sync(c, ah, bl, c);
        }
        wmma::store_matrix_sync(cs, c, 16, wmma::mem_row_major);
        __syncwarp();
#pragma unroll
        for (int i = 0; i < 8; i++) {
            int idx = lane + i * 32;        // 0..255
            int r = idx >> 4, cc = idx & 15;
            int col = nt * 16 + cc;
            float v = fmaxf(cs[r * 16 + cc] * inv_all + __ldg(&b1[col]), 0.f) * s;
            __half hh = __float2half_rn(v);
            th[r * TSH + col] = hh;
            tl[r * TSH + col] = __float2half_rn(v - __half2float(hh));
        }
        __syncwarp();
    }

    // ---- GEMM2: cs = (T*s)@(W2*256);  out = relu(cs*inv_all + b2 [+ h]) + xin
#pragma unroll
    for (int nt = 0; nt < 8; nt++) {
        CH c;
        wmma::fill_fragment(c, 0.f);
#pragma unroll
        for (int k = 0; k < 8; k++) {
            wmma::load_matrix_sync(ah, th + k * 16, TSH);
            wmma::load_matrix_sync(al, tl + k * 16, TSH);
            wmma::load_matrix_sync(bh, W2h + (size_t)(k * 16) * HID + nt * 16, HID);
            wmma::load_matrix_sync(bl, W2l + (size_t)(k * 16) * HID + nt * 16, HID);
            wmma::mma_sync(c, ah, bh, c);
            wmma::mma_sync(c, al, bh, c);
            wmma::mma_sync(c, ah, bl, c);
        }
        wmma::store_matrix_sync(cs, c, 16, wmma::mem_row_major);
        __syncwarp();
#pragma unroll
        for (int i = 0; i < 8; i++) {
            int idx = lane + i * 32;
            int r = idx >> 4, cc = idx & 15;
            int grow = wrow + r;
            if (grow < N_NODES) {
                int col = nt * 16 + cc;
                size_t base = (size_t)grow * HID + col;
                float v = cs[r * 16 + cc] * inv_all + __ldg(&b2[col]);
                if (add_h) v += g_h[base];
                g_x[base] = fmaxf(v, 0.f) + xin[base];
            }
        }
        __syncwarp();
    }
}

// ---------------- mean pool over sorted batch ----------------
#define POOL_CHUNK 256
__global__ void pool_kernel(const int* __restrict__ batch) {
    int d = threadIdx.x;  // 128
    int n0 = blockIdx.x * POOL_CHUNK;
    int n1 = n0 + POOL_CHUNK; if (n1 > N_NODES) n1 = N_NODES;
    int cur = batch[n0];
    float local = 0.f;
    for (int n = n0; n < n1; n++) {
        int b = batch[n];
        if (b != cur) {
            atomicAdd(&g_pool[cur * HID + d], local);
            local = 0.f; cur = b;
        }
        local += g_x[(size_t)n * HID + d];
    }
    atomicAdd(&g_pool[cur * HID + d], local);
    if (d == 0) {
        int c2 = batch[n0];
        float cl = 0.f;
        for (int n = n0; n < n1; n++) {
            int b = batch[n];
            if (b != c2) { atomicAdd(&g_cnt[c2], cl); cl = 0.f; c2 = b; }
            cl += 1.f;
        }
        atomicAdd(&g_cnt[c2], cl);
    }
}

// ---------------- classifier ----------------
__global__ void cls1_kernel(const float* __restrict__ Wc1,
                            const float* __restrict__ bc1) {
    __shared__ float Ps[128];
    int g = blockIdx.x;
    int t = threadIdx.x;
    float inv = 1.f / fmaxf(g_cnt[g], 1.f);
    Ps[t] = g_pool[g * HID + t] * inv;
    __syncthreads();
    float s = bc1[t];
#pragma unroll 4
    for (int k = 0; k < 128; k++) s += Ps[k] * __ldg(&Wc1[k * 128 + t]);
    g_cls[g * HID + t] = fmaxf(s, 0.f);
}

__global__ void cls2_kernel(const float* __restrict__ Wc2,
                            const float* __restrict__ bc2,
                            float* __restrict__ out) {
    int t = threadIdx.x;
    int g = t >> 1, c = t & 1;
    float s = bc2[c];
#pragma unroll 4
    for (int k = 0; k < 128; k++) s += g_cls[g * HID + k] * __ldg(&Wc2[k * 2 + c]);
    out[t] = s;
}

// ---------------- launch (pure kernel launches — graph-capture safe) -------------
// NOTE: never do pointer arithmetic on __device__ symbols here (host shadow trap).
extern "C" void kernel_launch(void* const* d_in, const int* in_sizes, int n_in,
                              void* d_out, int out_size) {
    const float* x     = (const float*)d_in[0];
    const int*   ei    = (const int*)d_in[1];     // int32 (JAX x64 disabled)
    const int*   batch = (const int*)d_in[2];     // int32
    const float* eps   = (const float*)d_in[3];
    const float* W1    = (const float*)d_in[4];
    const float* b1    = (const float*)d_in[5];
    const float* W2    = (const float*)d_in[6];
    const float* b2    = (const float*)d_in[7];
    const float* Wc1   = (const float*)d_in[8];
    const float* bc1   = (const float*)d_in[9];
    const float* Wc2   = (const float*)d_in[10];
    const float* bc2   = (const float*)d_in[11];
    const int* src = ei;
    const int* dst = ei + N_EDGES;

    const int nblk_scan = (N_NODES + 511) / 512;            // 196
    const int nblk_mlp  = (N_NODES + WM_BM - 1) / WM_BM;    // 1563

    wprep_kernel<<<(NUM_LAYERS * HID * HID + 255) / 256, 256>>>(W1, W2);
    zero_kernel<<<(N_NODES + 255) / 256, 256>>>();
    hist_kernel<<<(N_EDGES + 255) / 256, 256>>>(dst);
    scan1_kernel<<<nblk_scan, 512>>>();
    scan2_kernel<<<1, 256>>>(nblk_scan);
    scan3_kernel<<<(N_NODES + 255) / 256, 256>>>();
    scatter_kernel<<<(N_EDGES + 255) / 256, 256>>>(src, dst);

    for (int i = 0; i < NUM_LAYERS; i++) {
        int use_gx = (i > 0) ? 1 : 0;
        aggr_kernel<<<(N_NODES + 7) / 8, 256>>>(x, eps, i, use_gx);
        split_kernel<<<(N_NODES * 32 + 255) / 256, 256>>>(i);
        mlp_h3_kernel<<<nblk_mlp, 128>>>(
            x,
            b1 + (size_t)i * HID, b2 + (size_t)i * HID,
            (i > 0) ? 1 : 0, use_gx, i);
    }

    pool_kernel<<<(N_NODES + POOL_CHUNK - 1) / POOL_CHUNK, 128>>>(batch);
    cls1_kernel<<<NUM_GRAPHS, 128>>>(Wc1, bc1);
    cls2_kernel<<<1, 128>>>(Wc2, bc2, (float*)d_out);
}